// round 1
// baseline (speedup 1.0000x reference)
#include <cuda_runtime.h>
#include <stdint.h>

#define BATCH 2
#define NBOX 16384
#define PRE 1024
#define POST 512
#define NMSW 16            // 1024 bits / 64
#define NMS_THRESH 0.8f

struct Box5 { float x, y, dx, dy, c, s, rad, area; };

__device__ int                g_topidx[BATCH][PRE];
__device__ Box5               g_box[BATCH][PRE];
__device__ float              g_cor[BATCH][PRE][8];      // x0,y0,x1,y1,x2,y2,x3,y3
__device__ unsigned long long g_mask[BATCH][PRE][NMSW];  // suppression bits (j>i)
__device__ unsigned long long g_keep[BATCH][NMSW];

// --------------------------------------------------------------------------
// Zero the pair mask (atomicOr accumulates; must reset every graph replay)
// --------------------------------------------------------------------------
__global__ void zero_kernel() {
    unsigned long long* p = &g_mask[0][0][0];
    int total = BATCH * PRE * NMSW;
    for (int i = blockIdx.x * blockDim.x + threadIdx.x; i < total;
         i += gridDim.x * blockDim.x)
        p[i] = 0ull;
}

// --------------------------------------------------------------------------
// Top-1024 selection, exact stable ordering (value desc, index asc).
// One CTA per batch: full bitonic sort of 16384 packed u64 keys in smem.
// --------------------------------------------------------------------------
__global__ void topk_kernel(const float* __restrict__ cls) {
    extern __shared__ unsigned long long skey[];
    int b = blockIdx.x;
    int tid = threadIdx.x;

    for (int i = tid; i < NBOX; i += blockDim.x) {
        const float* p = cls + ((long)b * NBOX + i) * 3;
        float sc = fmaxf(p[0], fmaxf(p[1], p[2]));
        unsigned u = __float_as_uint(sc);
        unsigned m = (u & 0x80000000u) ? ~u : (u | 0x80000000u); // ascending monotone
        skey[i] = (((unsigned long long)(~m)) << 32) | (unsigned)i; // sort asc => score desc, idx asc
    }
    __syncthreads();

    for (unsigned k = 2; k <= NBOX; k <<= 1) {
        for (unsigned j = k >> 1; j > 0; j >>= 1) {
            for (unsigned i = tid; i < NBOX; i += blockDim.x) {
                unsigned ixj = i ^ j;
                if (ixj > i) {
                    bool up = ((i & k) == 0);
                    unsigned long long a = skey[i];
                    unsigned long long c = skey[ixj];
                    if ((a > c) == up) { skey[i] = c; skey[ixj] = a; }
                }
            }
            __syncthreads();
        }
    }
    if (tid < PRE)
        g_topidx[b][tid] = (int)(skey[tid] & 0xFFFFFFFFull);
}

// --------------------------------------------------------------------------
// Precompute per-box BEV params + corners
// --------------------------------------------------------------------------
__global__ void prep_kernel(const float* __restrict__ boxes) {
    int b = blockIdx.x;
    int i = threadIdx.x;
    int idx = g_topidx[b][i];
    const float* bp = boxes + ((long)b * NBOX + idx) * 7;
    float x = bp[0], y = bp[1], dx = bp[3], dy = bp[4], r = bp[6];
    float c = cosf(r), s = sinf(r);
    Box5 bx;
    bx.x = x; bx.y = y; bx.dx = dx; bx.dy = dy; bx.c = c; bx.s = s;
    bx.rad = 0.5f * sqrtf(dx * dx + dy * dy);
    bx.area = dx * dy;
    g_box[b][i] = bx;
    const float ox[4] = {0.5f, -0.5f, -0.5f, 0.5f};
    const float oy[4] = {0.5f, 0.5f, -0.5f, -0.5f};
    float* co = g_cor[b][i];
#pragma unroll
    for (int k = 0; k < 4; k++) {
        float lx = dx * ox[k], ly = dy * oy[k];
        co[2 * k]     = x + lx * c - ly * s;
        co[2 * k + 1] = y + lx * s + ly * c;
    }
}

// --------------------------------------------------------------------------
// Reference-faithful rotated BEV IoU (fp32, same formulas/ordering/tolerances)
// --------------------------------------------------------------------------
__device__ float rotated_iou(const Box5& A, const float* __restrict__ CA,
                             const Box5& Bx, const float* __restrict__ CB) {
    float ptsx[24], ptsy[24];
    bool mk[24];

    float axv[4], ayv[4], dax[4], day[4];
    float bxv[4], byv[4], dbx[4], dby[4];
#pragma unroll
    for (int k = 0; k < 4; k++) {
        axv[k] = CA[2 * k]; ayv[k] = CA[2 * k + 1];
        bxv[k] = CB[2 * k]; byv[k] = CB[2 * k + 1];
    }
#pragma unroll
    for (int k = 0; k < 4; k++) {
        int k1 = (k + 1) & 3;
        dax[k] = axv[k1] - axv[k]; day[k] = ayv[k1] - ayv[k];
        dbx[k] = bxv[k1] - bxv[k]; dby[k] = byv[k1] - byv[k];
    }

    // 16 edge-edge intersections, index = p*4 + q (a-edge major)
#pragma unroll
    for (int p = 0; p < 4; p++) {
#pragma unroll
        for (int q = 0; q < 4; q++) {
            int id = p * 4 + q;
            float den = dax[p] * dby[q] - day[p] * dbx[q];
            float ddx = bxv[q] - axv[p];
            float ddy = byv[q] - ayv[p];
            bool denok = fabsf(den) > 1e-8f;
            float dens = denok ? den : 1.0f;
            float t = (ddx * dby[q] - ddy * dbx[q]) / dens;
            float u = (ddx * day[p] - ddy * dax[p]) / dens;
            bool ok = denok && (t >= 0.0f) && (t <= 1.0f) && (u >= 0.0f) && (u <= 1.0f);
            mk[id] = ok;
            ptsx[id] = axv[p] + t * dax[p];
            ptsy[id] = ayv[p] + t * day[p];
        }
    }
    // corners of A in B (tolerance 1e-5), ids 16..19
#pragma unroll
    for (int k = 0; k < 4; k++) {
        float rx = axv[k] - Bx.x, ry = ayv[k] - Bx.y;
        float qx = rx * Bx.c + ry * Bx.s;
        float qy = -rx * Bx.s + ry * Bx.c;
        mk[16 + k] = (fabsf(qx) <= Bx.dx * 0.5f + 1e-5f) &&
                     (fabsf(qy) <= Bx.dy * 0.5f + 1e-5f);
        ptsx[16 + k] = axv[k]; ptsy[16 + k] = ayv[k];
    }
    // corners of B in A, ids 20..23
#pragma unroll
    for (int k = 0; k < 4; k++) {
        float rx = bxv[k] - A.x, ry = byv[k] - A.y;
        float qx = rx * A.c + ry * A.s;
        float qy = -rx * A.s + ry * A.c;
        mk[20 + k] = (fabsf(qx) <= A.dx * 0.5f + 1e-5f) &&
                     (fabsf(qy) <= A.dy * 0.5f + 1e-5f);
        ptsx[20 + k] = bxv[k]; ptsy[20 + k] = byv[k];
    }

    // masked centroid
    int cnt = 0;
    float sx = 0.0f, sy = 0.0f;
#pragma unroll
    for (int k = 0; k < 24; k++)
        if (mk[k]) { cnt++; sx += ptsx[k]; sy += ptsy[k]; }
    float cf = (float)(cnt > 1 ? cnt : 1);
    float cx = sx / cf, cy = sy / cf;

    // angles (masked -> 1e9) and STABLE ascending sort (insertion, strict >)
    float ang[24];
#pragma unroll
    for (int k = 0; k < 24; k++)
        ang[k] = mk[k] ? atan2f(ptsy[k] - cy, ptsx[k] - cx) : 1e9f;

    for (int i = 1; i < 24; i++) {
        float a0 = ang[i], x0 = ptsx[i], y0 = ptsy[i];
        bool m0 = mk[i];
        int j = i;
        while (j > 0 && ang[j - 1] > a0) {
            ang[j] = ang[j - 1]; ptsx[j] = ptsx[j - 1];
            ptsy[j] = ptsy[j - 1]; mk[j] = mk[j - 1];
            j--;
        }
        ang[j] = a0; ptsx[j] = x0; ptsy[j] = y0; mk[j] = m0;
    }

    // polygon: masked slots replaced by first sorted point; shoelace
    float fx = ptsx[0], fy = ptsy[0];
    float qxv[24], qyv[24];
#pragma unroll
    for (int k = 0; k < 24; k++) {
        qxv[k] = mk[k] ? ptsx[k] : fx;
        qyv[k] = mk[k] ? ptsy[k] : fy;
    }
    float s2 = 0.0f;
#pragma unroll
    for (int k = 0; k < 24; k++) {
        int k1 = (k + 1) % 24;
        s2 += qxv[k] * qyv[k1] - qyv[k] * qxv[k1];
    }
    float inter = 0.5f * fabsf(s2);
    float un = A.area + Bx.area - inter;
    un = fmaxf(un, 1e-6f);
    return inter / un;
}

// --------------------------------------------------------------------------
// Pairwise suppression-mask kernel: circle prefilter, then exact IoU
// --------------------------------------------------------------------------
__global__ void pair_kernel() {
    int b = blockIdx.y;
    int t = blockIdx.x * blockDim.x + threadIdx.x;
    int i = t >> 10;
    int j = t & (PRE - 1);
    if (j <= i) return;

    Box5 A = g_box[b][i];
    Box5 Bx = g_box[b][j];
    float ddx = A.x - Bx.x, ddy = A.y - Bx.y;
    float d2 = ddx * ddx + ddy * ddy;
    float rr = A.rad + Bx.rad + 1e-2f;
    if (d2 > rr * rr) return;   // disjoint => iou ~ 0 << 0.8

    float iou = rotated_iou(A, g_cor[b][i], Bx, g_cor[b][j]);
    if (iou > NMS_THRESH)
        atomicOr(&g_mask[b][i][j >> 6], 1ull << (j & 63));
}

// --------------------------------------------------------------------------
// Greedy NMS: serial 1024-step sweep, 16 lanes hold the 1024-bit supp set
// --------------------------------------------------------------------------
__global__ void nms_kernel() {
    int b = blockIdx.x;
    int lane = threadIdx.x;
    unsigned long long S = 0ull;
    for (int i = 0; i < PRE; i++) {
        unsigned long long row = (lane < NMSW) ? g_mask[b][i][lane] : 0ull;
        unsigned long long Sw = __shfl_sync(0xffffffffu, S, i >> 6);
        bool suppressed = (Sw >> (i & 63)) & 1ull;
        if (!suppressed) S |= row;
    }
    if (lane < NMSW) g_keep[b][lane] = ~S;
}

// --------------------------------------------------------------------------
// Compact kept indices (already in ascending priority order) + gather output.
// Output layout (float32): rois[B,512,7] | scores[B,512] | labels[B,512] | logits[B,512,3]
// --------------------------------------------------------------------------
__global__ void out_kernel(const float* __restrict__ boxes,
                           const float* __restrict__ cls,
                           float* __restrict__ out, int out_size) {
    int b = blockIdx.x;
    int s = threadIdx.x;  // 0..511

    // find the s-th set bit of g_keep[b]
    int pos = -1, c = 0;
    for (int w = 0; w < NMSW; w++) {
        unsigned long long kv = g_keep[b][w];
        int pc = __popcll(kv);
        if (pos < 0 && c + pc > s) {
            int r = s - c;
            for (int t = 0; t < r; t++) kv &= kv - 1ull;
            pos = w * 64 + __ffsll((long long)kv) - 1;
        }
        c += pc;
    }
    bool valid = pos >= 0;
    int p = valid ? pos : (PRE - 1);
    int sel = g_topidx[b][p];

    const float* bp = boxes + ((long)b * NBOX + sel) * 7;
    const float* lp = cls + ((long)b * NBOX + sel) * 3;
    float l0 = lp[0], l1 = lp[1], l2 = lp[2];
    float sc = l0; int lab = 0;
    if (l1 > sc) { sc = l1; lab = 1; }
    if (l2 > sc) { sc = l2; lab = 2; }

    const int ROIS_OFF = 0;
    const int SC_OFF = BATCH * POST * 7;          // 7168
    const int LB_OFF = SC_OFF + BATCH * POST;     // 8192
    const int LG_OFF = LB_OFF + BATCH * POST;     // 9216
    int base = b * POST + s;

#pragma unroll
    for (int k = 0; k < 7; k++) {
        int o = ROIS_OFF + base * 7 + k;
        if (o < out_size) out[o] = valid ? bp[k] : 0.0f;
    }
    {
        int o = SC_OFF + base;
        if (o < out_size) out[o] = valid ? sc : 0.0f;
    }
    {
        int o = LB_OFF + base;
        if (o < out_size) out[o] = valid ? (float)(lab + 1) : 1.0f;
    }
    {
        float lg[3] = {l0, l1, l2};
#pragma unroll
        for (int k = 0; k < 3; k++) {
            int o = LG_OFF + base * 3 + k;
            if (o < out_size) out[o] = valid ? lg[k] : 0.0f;
        }
    }
}

// --------------------------------------------------------------------------
extern "C" void kernel_launch(void* const* d_in, const int* in_sizes, int n_in,
                              void* d_out, int out_size) {
    const float* boxes = (const float*)d_in[0];  // [2,16384,7]
    const float* cls = (const float*)d_in[1];    // [2,16384,3]
    float* out = (float*)d_out;

    cudaFuncSetAttribute(topk_kernel,
                         cudaFuncAttributeMaxDynamicSharedMemorySize,
                         NBOX * (int)sizeof(unsigned long long));

    zero_kernel<<<128, 256>>>();
    topk_kernel<<<BATCH, 1024, NBOX * sizeof(unsigned long long)>>>(cls);
    prep_kernel<<<BATCH, PRE>>>(boxes);
    dim3 pg((PRE * PRE) / 256, BATCH);
    pair_kernel<<<pg, 256>>>();
    nms_kernel<<<BATCH, 32>>>();
    out_kernel<<<BATCH, POST>>>(boxes, cls, out, out_size);
}

// round 2
// speedup vs baseline: 2.3725x; 2.3725x over previous
#include <cuda_runtime.h>
#include <stdint.h>

#define BATCH 2
#define NBOX 16384
#define PRE 1024
#define POST 512
#define NMSW 16            // 1024 bits / 64
#define NMS_THRESH 0.8f
#define HBINS 65536
#define CAND_CAP 2048
#define SORT_N 2048
#define PAIR_CAP 65536

struct Box5 { float x, y, dx, dy, c, s, rad, area; };

__device__ int                g_topidx[BATCH][PRE];
__device__ Box5               g_box[BATCH][PRE];
__device__ float              g_cor[BATCH][PRE][8];
__device__ unsigned long long g_mask[BATCH][PRE][NMSW];
__device__ unsigned long long g_keep[BATCH][NMSW];
__device__ unsigned           g_hist[BATCH][HBINS];
__device__ unsigned           g_thresh[BATCH];
__device__ int                g_ccount[BATCH];
__device__ unsigned long long g_cand[BATCH][CAND_CAP];
__device__ int                g_paircount;
__device__ unsigned           g_pairs[PAIR_CAP];   // b<<20 | i<<10 | j

// --------------------------------------------------------------------------
// Zero all accumulation state (graph replays reuse it)
// --------------------------------------------------------------------------
__global__ void zero_kernel() {
    int tid = blockIdx.x * blockDim.x + threadIdx.x;
    int stride = gridDim.x * blockDim.x;
    unsigned long long* pm = &g_mask[0][0][0];
    for (int i = tid; i < BATCH * PRE * NMSW; i += stride) pm[i] = 0ull;
    unsigned* ph = &g_hist[0][0];
    for (int i = tid; i < BATCH * HBINS; i += stride) ph[i] = 0u;
    if (tid < BATCH) g_ccount[tid] = 0;
    if (tid == 0) g_paircount = 0;
}

// --------------------------------------------------------------------------
// Packed sort key: ascending u64 order == score desc, index asc (stable topk)
// --------------------------------------------------------------------------
__device__ __forceinline__ unsigned long long make_key(const float* __restrict__ cls,
                                                       int b, int i) {
    const float* p = cls + ((long)b * NBOX + i) * 3;
    float sc = fmaxf(p[0], fmaxf(p[1], p[2]));
    unsigned u = __float_as_uint(sc);
    unsigned m = (u & 0x80000000u) ? ~u : (u | 0x80000000u);
    return (((unsigned long long)(~m)) << 32) | (unsigned)i;
}

__global__ void hist_kernel(const float* __restrict__ cls) {
    int t = blockIdx.x * blockDim.x + threadIdx.x;
    if (t >= BATCH * NBOX) return;
    int b = t >> 14, i = t & (NBOX - 1);
    unsigned long long k = make_key(cls, b, i);
    atomicAdd(&g_hist[b][(unsigned)(k >> 48)], 1u);
}

// Find the smallest 16-bit bin T such that count(key_high16 <= T) >= PRE
__global__ void scan_kernel() {
    __shared__ unsigned part[1024];
    int b = blockIdx.x, t = threadIdx.x;
    unsigned s = 0;
    const unsigned* h = g_hist[b];
#pragma unroll
    for (int k = 0; k < 64; k++) s += h[t * 64 + k];
    part[t] = s;
    __syncthreads();
    // inclusive scan (Hillis-Steele)
    for (int off = 1; off < 1024; off <<= 1) {
        unsigned v = (t >= off) ? part[t - off] : 0u;
        __syncthreads();
        part[t] += v;
        __syncthreads();
    }
    unsigned incl = part[t];
    unsigned excl = (t == 0) ? 0u : part[t - 1];
    if (incl >= PRE && excl < PRE) {
        unsigned c = excl;
        for (int k = 0; k < 64; k++) {
            c += h[t * 64 + k];
            if (c >= PRE) { g_thresh[b] = (unsigned)(t * 64 + k); break; }
        }
    }
}

__global__ void compact_kernel(const float* __restrict__ cls) {
    int t = blockIdx.x * blockDim.x + threadIdx.x;
    if (t >= BATCH * NBOX) return;
    int b = t >> 14, i = t & (NBOX - 1);
    unsigned long long k = make_key(cls, b, i);
    if ((unsigned)(k >> 48) <= g_thresh[b]) {
        int pos = atomicAdd(&g_ccount[b], 1);
        if (pos < CAND_CAP) g_cand[b][pos] = k;
    }
}

// Bitonic sort of SORT_N candidates (one CTA per batch, smem), take first PRE
__global__ void sort_kernel() {
    __shared__ unsigned long long skey[SORT_N];
    int b = blockIdx.x, tid = threadIdx.x;
    int m = g_ccount[b];
    if (m > CAND_CAP) m = CAND_CAP;
#pragma unroll
    for (int r = 0; r < SORT_N / 1024; r++) {
        int i = tid + r * 1024;
        skey[i] = (i < m) ? g_cand[b][i] : ~0ull;
    }
    __syncthreads();
    for (unsigned k = 2; k <= SORT_N; k <<= 1) {
        for (unsigned j = k >> 1; j > 0; j >>= 1) {
            unsigned i = tid;  // 1024 threads handle SORT_N/2 compare pairs
            {
                unsigned lo = (i / j) * (2 * j) + (i % j);  // wrong mapping? use classic
            }
            // classic mapping over all indices
            for (unsigned idx = tid; idx < SORT_N; idx += 1024) {
                unsigned ixj = idx ^ j;
                if (ixj > idx) {
                    bool up = ((idx & k) == 0);
                    unsigned long long a = skey[idx];
                    unsigned long long c = skey[ixj];
                    if ((a > c) == up) { skey[idx] = c; skey[ixj] = a; }
                }
            }
            __syncthreads();
        }
    }
    if (tid < PRE) g_topidx[b][tid] = (int)(skey[tid] & 0xFFFFFFFFull);
}

// --------------------------------------------------------------------------
// Per-box BEV params + corners
// --------------------------------------------------------------------------
__global__ void prep_kernel(const float* __restrict__ boxes) {
    int b = blockIdx.x;
    int i = threadIdx.x;
    int idx = g_topidx[b][i];
    const float* bp = boxes + ((long)b * NBOX + idx) * 7;
    float x = bp[0], y = bp[1], dx = bp[3], dy = bp[4], r = bp[6];
    float c = cosf(r), s = sinf(r);
    Box5 bx;
    bx.x = x; bx.y = y; bx.dx = dx; bx.dy = dy; bx.c = c; bx.s = s;
    bx.rad = 0.5f * sqrtf(dx * dx + dy * dy);
    bx.area = dx * dy;
    g_box[b][i] = bx;
    const float ox[4] = {0.5f, -0.5f, -0.5f, 0.5f};
    const float oy[4] = {0.5f, 0.5f, -0.5f, -0.5f};
    float* co = g_cor[b][i];
#pragma unroll
    for (int k = 0; k < 4; k++) {
        float lx = dx * ox[k], ly = dy * oy[k];
        co[2 * k]     = x + lx * c - ly * s;
        co[2 * k + 1] = y + lx * s + ly * c;
    }
}

// --------------------------------------------------------------------------
// Reference-faithful rotated BEV IoU
// --------------------------------------------------------------------------
__device__ float rotated_iou(const Box5& A, const float* __restrict__ CA,
                             const Box5& Bx, const float* __restrict__ CB) {
    float ptsx[24], ptsy[24];
    bool mk[24];
    float axv[4], ayv[4], dax[4], day[4];
    float bxv[4], byv[4], dbx[4], dby[4];
#pragma unroll
    for (int k = 0; k < 4; k++) {
        axv[k] = CA[2 * k]; ayv[k] = CA[2 * k + 1];
        bxv[k] = CB[2 * k]; byv[k] = CB[2 * k + 1];
    }
#pragma unroll
    for (int k = 0; k < 4; k++) {
        int k1 = (k + 1) & 3;
        dax[k] = axv[k1] - axv[k]; day[k] = ayv[k1] - ayv[k];
        dbx[k] = bxv[k1] - bxv[k]; dby[k] = byv[k1] - byv[k];
    }
#pragma unroll
    for (int p = 0; p < 4; p++) {
#pragma unroll
        for (int q = 0; q < 4; q++) {
            int id = p * 4 + q;
            float den = dax[p] * dby[q] - day[p] * dbx[q];
            float ddx = bxv[q] - axv[p];
            float ddy = byv[q] - ayv[p];
            bool denok = fabsf(den) > 1e-8f;
            float dens = denok ? den : 1.0f;
            float t = (ddx * dby[q] - ddy * dbx[q]) / dens;
            float u = (ddx * day[p] - ddy * dax[p]) / dens;
            bool ok = denok && (t >= 0.0f) && (t <= 1.0f) && (u >= 0.0f) && (u <= 1.0f);
            mk[id] = ok;
            ptsx[id] = axv[p] + t * dax[p];
            ptsy[id] = ayv[p] + t * day[p];
        }
    }
#pragma unroll
    for (int k = 0; k < 4; k++) {
        float rx = axv[k] - Bx.x, ry = ayv[k] - Bx.y;
        float qx = rx * Bx.c + ry * Bx.s;
        float qy = -rx * Bx.s + ry * Bx.c;
        mk[16 + k] = (fabsf(qx) <= Bx.dx * 0.5f + 1e-5f) &&
                     (fabsf(qy) <= Bx.dy * 0.5f + 1e-5f);
        ptsx[16 + k] = axv[k]; ptsy[16 + k] = ayv[k];
    }
#pragma unroll
    for (int k = 0; k < 4; k++) {
        float rx = bxv[k] - A.x, ry = byv[k] - A.y;
        float qx = rx * A.c + ry * A.s;
        float qy = -rx * A.s + ry * A.c;
        mk[20 + k] = (fabsf(qx) <= A.dx * 0.5f + 1e-5f) &&
                     (fabsf(qy) <= A.dy * 0.5f + 1e-5f);
        ptsx[20 + k] = bxv[k]; ptsy[20 + k] = byv[k];
    }

    int cnt = 0;
    float sx = 0.0f, sy = 0.0f;
#pragma unroll
    for (int k = 0; k < 24; k++)
        if (mk[k]) { cnt++; sx += ptsx[k]; sy += ptsy[k]; }
    float cf = (float)(cnt > 1 ? cnt : 1);
    float cx = sx / cf, cy = sy / cf;

    float ang[24];
#pragma unroll
    for (int k = 0; k < 24; k++)
        ang[k] = mk[k] ? atan2f(ptsy[k] - cy, ptsx[k] - cx) : 1e9f;

    for (int i = 1; i < 24; i++) {
        float a0 = ang[i], x0 = ptsx[i], y0 = ptsy[i];
        bool m0 = mk[i];
        int j = i;
        while (j > 0 && ang[j - 1] > a0) {
            ang[j] = ang[j - 1]; ptsx[j] = ptsx[j - 1];
            ptsy[j] = ptsy[j - 1]; mk[j] = mk[j - 1];
            j--;
        }
        ang[j] = a0; ptsx[j] = x0; ptsy[j] = y0; mk[j] = m0;
    }

    float fx = ptsx[0], fy = ptsy[0];
    float qxv[24], qyv[24];
#pragma unroll
    for (int k = 0; k < 24; k++) {
        qxv[k] = mk[k] ? ptsx[k] : fx;
        qyv[k] = mk[k] ? ptsy[k] : fy;
    }
    float s2 = 0.0f;
#pragma unroll
    for (int k = 0; k < 24; k++) {
        int k1 = (k + 1) % 24;
        s2 += qxv[k] * qyv[k1] - qyv[k] * qxv[k1];
    }
    float inter = 0.5f * fabsf(s2);
    float un = fmaxf(A.area + Bx.area - inter, 1e-6f);
    return inter / un;
}

// --------------------------------------------------------------------------
// Phase A: dense prefilter -> compact surviving pair list
// iou <= min(area)/max(area) bound + bounding-circle test
// --------------------------------------------------------------------------
__global__ void prefilter_kernel() {
    int b = blockIdx.y;
    int t = blockIdx.x * blockDim.x + threadIdx.x;
    int i = t >> 10;
    int j = t & (PRE - 1);
    if (j <= i) return;
    Box5 A = g_box[b][i];
    Box5 Bx = g_box[b][j];
    float amin = fminf(A.area, Bx.area);
    float amax = fmaxf(A.area, Bx.area);
    if (amin < 0.795f * amax) return;         // iou <= amin/amax < thresh
    float ddx = A.x - Bx.x, ddy = A.y - Bx.y;
    float rr = A.rad + Bx.rad + 1e-2f;
    if (ddx * ddx + ddy * ddy > rr * rr) return;
    int pos = atomicAdd(&g_paircount, 1);
    if (pos < PAIR_CAP) g_pairs[pos] = ((unsigned)b << 20) | ((unsigned)i << 10) | (unsigned)j;
}

// --------------------------------------------------------------------------
// Phase B: dense exact IoU over survivors
// --------------------------------------------------------------------------
__global__ void heavy_kernel() {
    int n = g_paircount;
    if (n > PAIR_CAP) n = PAIR_CAP;
    for (int t = blockIdx.x * blockDim.x + threadIdx.x; t < n;
         t += gridDim.x * blockDim.x) {
        unsigned pk = g_pairs[t];
        int b = pk >> 20;
        int i = (pk >> 10) & 1023;
        int j = pk & 1023;
        Box5 A = g_box[b][i];
        Box5 Bx = g_box[b][j];
        float iou = rotated_iou(A, g_cor[b][i], Bx, g_cor[b][j]);
        if (iou > NMS_THRESH)
            atomicOr(&g_mask[b][i][j >> 6], 1ull << (j & 63));
    }
}

// --------------------------------------------------------------------------
// Greedy NMS sweep from smem
// --------------------------------------------------------------------------
__global__ void nms_kernel() {
    extern __shared__ unsigned long long sm[];   // PRE * NMSW
    int b = blockIdx.x;
    const unsigned long long* src = &g_mask[b][0][0];
    for (int i = threadIdx.x; i < PRE * NMSW; i += blockDim.x) sm[i] = src[i];
    __syncthreads();
    if (threadIdx.x < 32) {
        int lane = threadIdx.x;
        unsigned long long S = 0ull;
        for (int i = 0; i < PRE; i++) {
            unsigned long long row = (lane < NMSW) ? sm[i * NMSW + lane] : 0ull;
            unsigned long long Sw = __shfl_sync(0xffffffffu, S, i >> 6);
            if (!((Sw >> (i & 63)) & 1ull)) S |= row;
        }
        if (lane < NMSW) g_keep[b][lane] = ~S;
    }
}

// --------------------------------------------------------------------------
// Output gather
// --------------------------------------------------------------------------
__global__ void out_kernel(const float* __restrict__ boxes,
                           const float* __restrict__ cls,
                           float* __restrict__ out, int out_size) {
    int b = blockIdx.x;
    int s = threadIdx.x;  // 0..511

    int pos = -1, c = 0;
    for (int w = 0; w < NMSW; w++) {
        unsigned long long kv = g_keep[b][w];
        int pc = __popcll(kv);
        if (pos < 0 && c + pc > s) {
            int r = s - c;
            for (int t = 0; t < r; t++) kv &= kv - 1ull;
            pos = w * 64 + __ffsll((long long)kv) - 1;
        }
        c += pc;
    }
    bool valid = pos >= 0;
    int p = valid ? pos : (PRE - 1);
    int sel = g_topidx[b][p];

    const float* bp = boxes + ((long)b * NBOX + sel) * 7;
    const float* lp = cls + ((long)b * NBOX + sel) * 3;
    float l0 = lp[0], l1 = lp[1], l2 = lp[2];
    float sc = l0; int lab = 0;
    if (l1 > sc) { sc = l1; lab = 1; }
    if (l2 > sc) { sc = l2; lab = 2; }

    const int ROIS_OFF = 0;
    const int SC_OFF = BATCH * POST * 7;
    const int LB_OFF = SC_OFF + BATCH * POST;
    const int LG_OFF = LB_OFF + BATCH * POST;
    int base = b * POST + s;

#pragma unroll
    for (int k = 0; k < 7; k++) {
        int o = ROIS_OFF + base * 7 + k;
        if (o < out_size) out[o] = valid ? bp[k] : 0.0f;
    }
    { int o = SC_OFF + base; if (o < out_size) out[o] = valid ? sc : 0.0f; }
    { int o = LB_OFF + base; if (o < out_size) out[o] = valid ? (float)(lab + 1) : 1.0f; }
    {
        float lg[3] = {l0, l1, l2};
#pragma unroll
        for (int k = 0; k < 3; k++) {
            int o = LG_OFF + base * 3 + k;
            if (o < out_size) out[o] = valid ? lg[k] : 0.0f;
        }
    }
}

// --------------------------------------------------------------------------
extern "C" void kernel_launch(void* const* d_in, const int* in_sizes, int n_in,
                              void* d_out, int out_size) {
    const float* boxes = (const float*)d_in[0];  // [2,16384,7]
    const float* cls = (const float*)d_in[1];    // [2,16384,3]
    float* out = (float*)d_out;

    static bool attr_set = false;
    if (!attr_set) {
        cudaFuncSetAttribute(nms_kernel,
                             cudaFuncAttributeMaxDynamicSharedMemorySize,
                             PRE * NMSW * (int)sizeof(unsigned long long));
        attr_set = true;
    }

    zero_kernel<<<256, 256>>>();
    hist_kernel<<<(BATCH * NBOX + 255) / 256, 256>>>(cls);
    scan_kernel<<<BATCH, 1024>>>();
    compact_kernel<<<(BATCH * NBOX + 255) / 256, 256>>>(cls);
    sort_kernel<<<BATCH, 1024>>>();
    prep_kernel<<<BATCH, PRE>>>(boxes);
    dim3 pg((PRE * PRE) / 256, BATCH);
    prefilter_kernel<<<pg, 256>>>();
    heavy_kernel<<<128, 128>>>();
    nms_kernel<<<BATCH, 1024, PRE * NMSW * sizeof(unsigned long long)>>>();
    out_kernel<<<BATCH, POST>>>(boxes, cls, out, out_size);
}

// round 3
// speedup vs baseline: 4.6588x; 1.9637x over previous
#include <cuda_runtime.h>
#include <stdint.h>

#define BATCH 2
#define NBOX 16384
#define PRE 1024
#define POST 512
#define NMSW 16            // 1024 bits / 64
#define NMS_THRESH 0.8f
#define CAND_CAP 2048
#define SORT_N 2048
#define PAIR_CAP 65536
#define NCELLX 13
#define NCELL (NCELLX * NCELLX)
#define TPB 1024

typedef unsigned long long u64;

struct __align__(16) Box5 { float x, y, dx, dy, c, s, rad, area; };

__device__ int    g_topidx[BATCH][PRE];
__device__ Box5   g_box[BATCH][PRE];
__device__ float  g_cor[BATCH][PRE][8];
__device__ float4 g_f4[BATCH][PRE];            // x, y, rad, area (filter SoA)
__device__ u64    g_mask[BATCH][PRE][NMSW];
__device__ u64    g_rowflag[BATCH][NMSW];
__device__ int    g_cellstart[BATCH][NCELL + 1];
__device__ int    g_cellbox[BATCH][PRE];
__device__ int    g_paircount;
__device__ unsigned g_pairs[PAIR_CAP];         // b<<20 | i<<10 | j

__device__ __forceinline__ int cell_of(float v) {
    int c = (int)floorf((v + 50.0f) * 0.125f);
    return c < 0 ? 0 : (c > NCELLX - 1 ? NCELLX - 1 : c);
}

__device__ __forceinline__ u64 make_key(const float* __restrict__ cls, int b, int i) {
    const float* p = cls + ((long)b * NBOX + i) * 3;
    float sc = fmaxf(p[0], fmaxf(p[1], p[2]));
    unsigned u = __float_as_uint(sc);
    unsigned m = (u & 0x80000000u) ? ~u : (u | 0x80000000u); // ascending monotone
    return (((u64)(~m)) << 32) | (unsigned)i;  // u64 asc == score desc, idx asc
}

// ==========================================================================
// Fused: state zeroing + exact stable top-1024 (radix threshold + bitonic)
//        + box prep + spatial binning.  One CTA per batch.
// ==========================================================================
__global__ void topk_kernel(const float* __restrict__ cls,
                            const float* __restrict__ boxes) {
    extern __shared__ char smraw[];
    u64*      skey   = (u64*)smraw;                       // 16384
    u64*      cand   = skey + NBOX;                       // 2048
    unsigned* hist   = (unsigned*)(cand + CAND_CAP);      // 256
    unsigned* sc     = hist + 256;                        // 8 scratch
    unsigned* ccnt   = sc + 8;                            // NCELL (+pad)
    unsigned* cstart = ccnt + 176;                        // NCELL+1 (+pad)

    int b = blockIdx.x;
    int tid = threadIdx.x;

    // ---- zero per-replay global state ----
    {
        u64* pm = &g_mask[b][0][0];
        for (int i = tid; i < PRE * NMSW; i += TPB) pm[i] = 0ull;
        if (tid < NMSW) g_rowflag[b][tid] = 0ull;
        if (tid == 0 && b == 0) g_paircount = 0;
    }
    if (tid < 256) hist[tid] = 0u;
    if (tid < NCELL) ccnt[tid] = 0u;
    __syncthreads();

    // ---- keys + pass-1 histogram (top 8 bits) ----
#pragma unroll
    for (int r = 0; r < NBOX / TPB; r++) {
        int i = tid + r * TPB;
        u64 k = make_key(cls, b, i);
        skey[i] = k;
        atomicAdd(&hist[(unsigned)(k >> 56)], 1u);
    }
    __syncthreads();
    if (tid == 0) {
        unsigned c = 0, B0 = 255, C0 = 0;
        for (int x = 0; x < 256; x++) {
            unsigned nc = c + hist[x];
            if (nc >= PRE) { B0 = (unsigned)x; C0 = c; break; }
            c = nc;
        }
        sc[0] = B0; sc[1] = C0;
    }
    __syncthreads();
    unsigned B0 = sc[0], C0 = sc[1];
    if (tid < 256) hist[tid] = 0u;
    __syncthreads();

    // ---- pass-2 histogram (next 8 bits within bin B0) ----
#pragma unroll
    for (int r = 0; r < NBOX / TPB; r++) {
        u64 k = skey[tid + r * TPB];
        if ((unsigned)(k >> 56) == B0)
            atomicAdd(&hist[(unsigned)(k >> 48) & 0xFFu], 1u);
    }
    __syncthreads();
    if (tid == 0) {
        unsigned c = C0, B1 = 255;
        for (int x = 0; x < 256; x++) {
            c += hist[x];
            if (c >= PRE) { B1 = (unsigned)x; break; }
        }
        sc[2] = (B0 << 8) | B1;
        sc[3] = 0;
    }
    __syncthreads();
    unsigned thresh = sc[2];

    // ---- compact candidates (count in [PRE, CAND_CAP]) ----
#pragma unroll
    for (int r = 0; r < NBOX / TPB; r++) {
        u64 k = skey[tid + r * TPB];
        if ((unsigned)(k >> 48) <= thresh) {
            unsigned pos = atomicAdd(&sc[3], 1u);
            if (pos < CAND_CAP) cand[pos] = k;
        }
    }
    __syncthreads();
    int m = (int)sc[3]; if (m > CAND_CAP) m = CAND_CAP;
#pragma unroll
    for (int r = 0; r < SORT_N / TPB; r++) {
        int i = tid + r * TPB;
        if (i >= m) cand[i] = ~0ull;
    }
    __syncthreads();

    // ---- bitonic sort of 2048 (ascending == score desc, idx asc) ----
    for (unsigned k = 2; k <= SORT_N; k <<= 1) {
        for (unsigned j = k >> 1; j > 0; j >>= 1) {
#pragma unroll
            for (int r = 0; r < SORT_N / TPB; r++) {
                unsigned idx = tid + r * TPB;
                unsigned ixj = idx ^ j;
                if (ixj > idx) {
                    bool up = ((idx & k) == 0);
                    u64 a = cand[idx], c = cand[ixj];
                    if ((a > c) == up) { cand[idx] = c; cand[ixj] = a; }
                }
            }
            __syncthreads();
        }
    }

    // ---- prep + cell binning (threads 0..1023) ----
    int mycell = -1;
    if (tid < PRE) {
        int idx = (int)(cand[tid] & 0xFFFFFFFFull);
        g_topidx[b][tid] = idx;
        const float* bp = boxes + ((long)b * NBOX + idx) * 7;
        float x = bp[0], y = bp[1], dx = bp[3], dy = bp[4], r = bp[6];
        float c = cosf(r), s = sinf(r);
        Box5 bx;
        bx.x = x; bx.y = y; bx.dx = dx; bx.dy = dy; bx.c = c; bx.s = s;
        bx.rad = 0.5f * sqrtf(dx * dx + dy * dy);
        bx.area = dx * dy;
        g_box[b][tid] = bx;
        g_f4[b][tid] = make_float4(x, y, bx.rad, bx.area);
        const float ox[4] = {0.5f, -0.5f, -0.5f, 0.5f};
        const float oy[4] = {0.5f, 0.5f, -0.5f, -0.5f};
        float* co = g_cor[b][tid];
#pragma unroll
        for (int k = 0; k < 4; k++) {
            float lx = dx * ox[k], ly = dy * oy[k];
            co[2 * k]     = x + lx * c - ly * s;
            co[2 * k + 1] = y + lx * s + ly * c;
        }
        mycell = cell_of(y) * NCELLX + cell_of(x);
        atomicAdd(&ccnt[mycell], 1u);
    }
    __syncthreads();
    if (tid == 0) {
        unsigned c = 0;
        for (int x = 0; x < NCELL; x++) { cstart[x] = c; c += ccnt[x]; }
        cstart[NCELL] = c;
    }
    __syncthreads();
    if (tid < NCELL) ccnt[tid] = 0u;
    __syncthreads();
    if (tid < PRE) {
        unsigned pos = cstart[mycell] + atomicAdd(&ccnt[mycell], 1u);
        g_cellbox[b][pos] = tid;
    }
    if (tid <= NCELL) g_cellstart[b][tid] = (int)cstart[tid];
}

// ==========================================================================
// Pair generation via spatial hash: one thread per (box, neighbor cell)
// ==========================================================================
__global__ void pairgen_kernel() {
    int t = blockIdx.x * blockDim.x + threadIdx.x;
    if (t >= BATCH * PRE * 9) return;
    int b = t / (PRE * 9);
    int rem = t - b * PRE * 9;
    int i = rem / 9;
    int n = rem - i * 9;
    float4 fa = g_f4[b][i];
    int cx = cell_of(fa.x) + (n % 3) - 1;
    int cy = cell_of(fa.y) + (n / 3) - 1;
    if (cx < 0 || cx >= NCELLX || cy < 0 || cy >= NCELLX) return;
    int c = cy * NCELLX + cx;
    int s = g_cellstart[b][c], e = g_cellstart[b][c + 1];
    for (int p = s; p < e; p++) {
        int j = g_cellbox[b][p];
        if (j <= i) continue;
        float4 fb = g_f4[b][j];
        float amin = fminf(fa.w, fb.w), amax = fmaxf(fa.w, fb.w);
        if (amin < 0.795f * amax) continue;       // iou <= amin/amax < thresh
        float ddx = fa.x - fb.x, ddy = fa.y - fb.y;
        float rr = fa.z + fb.z + 1e-2f;
        if (ddx * ddx + ddy * ddy > rr * rr) continue;
        int pos = atomicAdd(&g_paircount, 1);
        if (pos < PAIR_CAP)
            g_pairs[pos] = ((unsigned)b << 20) | ((unsigned)i << 10) | (unsigned)j;
    }
}

// ==========================================================================
// Reference-faithful rotated BEV IoU
// ==========================================================================
__device__ float rotated_iou(const Box5& A, const float* __restrict__ CA,
                             const Box5& Bx, const float* __restrict__ CB) {
    float ptsx[24], ptsy[24];
    bool mk[24];
    float axv[4], ayv[4], dax[4], day[4];
    float bxv[4], byv[4], dbx[4], dby[4];
#pragma unroll
    for (int k = 0; k < 4; k++) {
        axv[k] = CA[2 * k]; ayv[k] = CA[2 * k + 1];
        bxv[k] = CB[2 * k]; byv[k] = CB[2 * k + 1];
    }
#pragma unroll
    for (int k = 0; k < 4; k++) {
        int k1 = (k + 1) & 3;
        dax[k] = axv[k1] - axv[k]; day[k] = ayv[k1] - ayv[k];
        dbx[k] = bxv[k1] - bxv[k]; dby[k] = byv[k1] - byv[k];
    }
#pragma unroll
    for (int p = 0; p < 4; p++) {
#pragma unroll
        for (int q = 0; q < 4; q++) {
            int id = p * 4 + q;
            float den = dax[p] * dby[q] - day[p] * dbx[q];
            float ddx = bxv[q] - axv[p];
            float ddy = byv[q] - ayv[p];
            bool denok = fabsf(den) > 1e-8f;
            float dens = denok ? den : 1.0f;
            float t = (ddx * dby[q] - ddy * dbx[q]) / dens;
            float u = (ddx * day[p] - ddy * dax[p]) / dens;
            bool ok = denok && (t >= 0.0f) && (t <= 1.0f) && (u >= 0.0f) && (u <= 1.0f);
            mk[id] = ok;
            ptsx[id] = axv[p] + t * dax[p];
            ptsy[id] = ayv[p] + t * day[p];
        }
    }
#pragma unroll
    for (int k = 0; k < 4; k++) {
        float rx = axv[k] - Bx.x, ry = ayv[k] - Bx.y;
        float qx = rx * Bx.c + ry * Bx.s;
        float qy = -rx * Bx.s + ry * Bx.c;
        mk[16 + k] = (fabsf(qx) <= Bx.dx * 0.5f + 1e-5f) &&
                     (fabsf(qy) <= Bx.dy * 0.5f + 1e-5f);
        ptsx[16 + k] = axv[k]; ptsy[16 + k] = ayv[k];
    }
#pragma unroll
    for (int k = 0; k < 4; k++) {
        float rx = bxv[k] - A.x, ry = byv[k] - A.y;
        float qx = rx * A.c + ry * A.s;
        float qy = -rx * A.s + ry * A.c;
        mk[20 + k] = (fabsf(qx) <= A.dx * 0.5f + 1e-5f) &&
                     (fabsf(qy) <= A.dy * 0.5f + 1e-5f);
        ptsx[20 + k] = bxv[k]; ptsy[20 + k] = byv[k];
    }

    int cnt = 0;
    float sx = 0.0f, sy = 0.0f;
#pragma unroll
    for (int k = 0; k < 24; k++)
        if (mk[k]) { cnt++; sx += ptsx[k]; sy += ptsy[k]; }
    float cf = (float)(cnt > 1 ? cnt : 1);
    float cx = sx / cf, cy = sy / cf;

    float ang[24];
#pragma unroll
    for (int k = 0; k < 24; k++)
        ang[k] = mk[k] ? atan2f(ptsy[k] - cy, ptsx[k] - cx) : 1e9f;

    for (int i = 1; i < 24; i++) {
        float a0 = ang[i], x0 = ptsx[i], y0 = ptsy[i];
        bool m0 = mk[i];
        int j = i;
        while (j > 0 && ang[j - 1] > a0) {
            ang[j] = ang[j - 1]; ptsx[j] = ptsx[j - 1];
            ptsy[j] = ptsy[j - 1]; mk[j] = mk[j - 1];
            j--;
        }
        ang[j] = a0; ptsx[j] = x0; ptsy[j] = y0; mk[j] = m0;
    }

    float fx = ptsx[0], fy = ptsy[0];
    float qxv[24], qyv[24];
#pragma unroll
    for (int k = 0; k < 24; k++) {
        qxv[k] = mk[k] ? ptsx[k] : fx;
        qyv[k] = mk[k] ? ptsy[k] : fy;
    }
    float s2 = 0.0f;
#pragma unroll
    for (int k = 0; k < 24; k++) {
        int k1 = (k + 1) % 24;
        s2 += qxv[k] * qyv[k1] - qyv[k] * qxv[k1];
    }
    float inter = 0.5f * fabsf(s2);
    float un = fmaxf(A.area + Bx.area - inter, 1e-6f);
    return inter / un;
}

// ==========================================================================
// Exact IoU over surviving pairs; flags rows that gained suppression bits
// ==========================================================================
__global__ void heavy_kernel() {
    int n = g_paircount;
    if (n > PAIR_CAP) n = PAIR_CAP;
    for (int t = blockIdx.x * blockDim.x + threadIdx.x; t < n;
         t += gridDim.x * blockDim.x) {
        unsigned pk = g_pairs[t];
        int b = pk >> 20;
        int i = (pk >> 10) & 1023;
        int j = pk & 1023;
        Box5 A = g_box[b][i];
        Box5 Bx = g_box[b][j];
        float iou = rotated_iou(A, g_cor[b][i], Bx, g_cor[b][j]);
        if (iou > NMS_THRESH) {
            atomicOr(&g_mask[b][i][j >> 6], 1ull << (j & 63));
            atomicOr(&g_rowflag[b][i >> 6], 1ull << (i & 63));
        }
    }
}

// ==========================================================================
// Fused sparse greedy NMS + output gather. One block (512 thr) per batch.
// ==========================================================================
__global__ void nms_out_kernel(const float* __restrict__ boxes,
                               const float* __restrict__ cls,
                               float* __restrict__ out, int out_size) {
    __shared__ int rows[PRE];
    __shared__ int Rcount;
    __shared__ u64 skeep[NMSW];
    int b = blockIdx.x;
    int tid = threadIdx.x;

    if (tid == 0) {
        int R = 0;
        for (int w = 0; w < NMSW; w++) {
            u64 f = g_rowflag[b][w];
            while (f) {
                int bit = __ffsll((long long)f) - 1;
                rows[R++] = w * 64 + bit;
                f &= f - 1ull;
            }
        }
        Rcount = R;
    }
    __syncthreads();
    int R = Rcount;

    if (tid < 32) {
        int lane = tid;
        u64 S = 0ull;
        for (int r = 0; r < R; r++) {
            int i = rows[r];
            u64 row = (lane < NMSW) ? g_mask[b][i][lane] : 0ull;
            u64 Sw = __shfl_sync(0xffffffffu, S, i >> 6);
            if (!((Sw >> (i & 63)) & 1ull)) S |= row;
        }
        if (lane < NMSW) skeep[lane] = ~S;
    }
    __syncthreads();

    // ---- output gather: thread s finds the s-th kept box ----
    int s = tid;
    if (s >= POST) return;
    int pos = -1, c = 0;
    for (int w = 0; w < NMSW; w++) {
        u64 kv = skeep[w];
        int pc = __popcll(kv);
        if (pos < 0 && c + pc > s) {
            int r = s - c;
            for (int t = 0; t < r; t++) kv &= kv - 1ull;
            pos = w * 64 + __ffsll((long long)kv) - 1;
        }
        c += pc;
    }
    bool valid = pos >= 0;
    int p = valid ? pos : (PRE - 1);
    int sel = g_topidx[b][p];

    const float* bp = boxes + ((long)b * NBOX + sel) * 7;
    const float* lp = cls + ((long)b * NBOX + sel) * 3;
    float l0 = lp[0], l1 = lp[1], l2 = lp[2];
    float scv = l0; int lab = 0;
    if (l1 > scv) { scv = l1; lab = 1; }
    if (l2 > scv) { scv = l2; lab = 2; }

    const int SC_OFF = BATCH * POST * 7;
    const int LB_OFF = SC_OFF + BATCH * POST;
    const int LG_OFF = LB_OFF + BATCH * POST;
    int base = b * POST + s;

#pragma unroll
    for (int k = 0; k < 7; k++) {
        int o = base * 7 + k;
        if (o < out_size) out[o] = valid ? bp[k] : 0.0f;
    }
    { int o = SC_OFF + base; if (o < out_size) out[o] = valid ? scv : 0.0f; }
    { int o = LB_OFF + base; if (o < out_size) out[o] = valid ? (float)(lab + 1) : 1.0f; }
    {
        float lg[3] = {l0, l1, l2};
#pragma unroll
        for (int k = 0; k < 3; k++) {
            int o = LG_OFF + base * 3 + k;
            if (o < out_size) out[o] = valid ? lg[k] : 0.0f;
        }
    }
}

// ==========================================================================
extern "C" void kernel_launch(void* const* d_in, const int* in_sizes, int n_in,
                              void* d_out, int out_size) {
    const float* boxes = (const float*)d_in[0];  // [2,16384,7]
    const float* cls = (const float*)d_in[1];    // [2,16384,3]
    float* out = (float*)d_out;

    const int SMEM_TOPK = NBOX * 8 + CAND_CAP * 8 + 256 * 4 + 8 * 4 +
                          176 * 4 + 176 * 4;     // ~150 KB

    static bool attr_set = false;
    if (!attr_set) {
        cudaFuncSetAttribute(topk_kernel,
                             cudaFuncAttributeMaxDynamicSharedMemorySize,
                             SMEM_TOPK);
        attr_set = true;
    }

    topk_kernel<<<BATCH, TPB, SMEM_TOPK>>>(cls, boxes);
    pairgen_kernel<<<(BATCH * PRE * 9 + 255) / 256, 256>>>();
    heavy_kernel<<<128, 128>>>();
    nms_out_kernel<<<BATCH, POST>>>(boxes, cls, out, out_size);
}